// round 2
// baseline (speedup 1.0000x reference)
#include <cuda_runtime.h>
#include <math.h>

#define Bb 128
#define Rr 1152
#define CI 8
#define Cc 10
#define Oo 16
#define RT 64
#define NRT (Rr/RT)     /* 18 */
#define NCB (Cc*Bb)     /* 1280 */
#define NS  (NCB*Oo)    /* 20480 */

// Scratch (static device arrays: allowed; no runtime allocation)
__device__ float g_u[(size_t)Cc*Bb*Rr*Oo];   // 94.4 MB: u[c][b][r][o]
__device__ float g_part[NS*NRT];             // per-r-tile partial sums of u
__device__ float g_S[NS];                    // s[c][b][o] per iteration
__device__ float g_V[NS];                    // accumulated v (== logits factor)

// ---------------------------------------------------------------------------
// K_u: u[c,b,r,o] = sum_i x[b,r,i] * W[c,r,i,o]
// grid: (NRT, C). Each CTA stages W[c, r-tile] (32KB) in smem once, then loops
// over all b, writing u and per-tile sums over r (for iteration 1's uniform
// softmax: s1 = mean_r u).
// ---------------------------------------------------------------------------
__global__ __launch_bounds__(256) void k_u(const float* __restrict__ x,
                                           const float* __restrict__ W) {
    const int rt = blockIdx.x;   // r tile
    const int c  = blockIdx.y;
    const int r0 = rt * RT;
    __shared__ float Wc[RT*CI*Oo];   // 32 KB
    __shared__ float xs[RT*CI];      // 2 KB
    __shared__ float red[256];

    const int tid = threadIdx.x;
    const float* Wsrc = W + ((size_t)(c*Rr + r0) * CI) * Oo;
    #pragma unroll
    for (int k = 0; k < (RT*CI*Oo)/256; k++)
        Wc[tid + k*256] = Wsrc[tid + k*256];

    const int o  = tid & 15;
    const int rl = tid >> 4;

    for (int b = 0; b < Bb; b++) {
        const float* xsrc = x + ((size_t)(b*Rr + r0)) * CI;
        xs[tid]       = xsrc[tid];
        xs[tid + 256] = xsrc[tid + 256];
        __syncthreads();

        float psum = 0.f;
        float* udst = g_u + ((size_t)(c*Bb + b)*Rr + r0) * Oo;
        #pragma unroll
        for (int k = 0; k < RT/16; k++) {
            const int r = rl + k*16;
            float acc = 0.f;
            #pragma unroll
            for (int i = 0; i < CI; i++)
                acc = fmaf(xs[r*CI + i], Wc[(r*CI + i)*Oo + o], acc);
            udst[r*Oo + o] = acc;
            psum += acc;
        }
        red[tid] = psum;
        __syncthreads();
        if (tid < 16) {
            float t = 0.f;
            #pragma unroll
            for (int j = 0; j < 16; j++) t += red[tid + j*16];
            g_part[((c*Bb + b)*Oo + tid)*NRT + rt] = t;
        }
        // red reads complete before next iteration's red write: guarded by
        // the __syncthreads() after the next xs load.
    }
}

// ---------------------------------------------------------------------------
// K_iter: per (c,b): logits[r,o] = u[r,o]*V[o]; softmax over r (shift-invariant,
// |u*V| is tiny so no max needed); s[o] = sum_r softmax * u.
// grid: (B, C), one streaming pass over u[c,b] (73.7 KB).
// ---------------------------------------------------------------------------
__global__ __launch_bounds__(256) void k_iter(void) {
    const int b = blockIdx.x, c = blockIdx.y;
    const int tid = threadIdx.x, o = tid & 15, rl = tid >> 4;
    const int cb = c*Bb + b;

    const float V = g_V[cb*Oo + o];
    const float* __restrict__ up = g_u + (size_t)cb * Rr * Oo;

    float z = 0.f, s = 0.f;
    #pragma unroll 8
    for (int r = rl; r < Rr; r += 16) {
        const float u = up[r*Oo + o];
        const float e = __expf(u * V);
        z += e;
        s += e * u;
    }

    __shared__ float zr[256], sr[256];
    zr[tid] = z; sr[tid] = s;
    __syncthreads();
    if (tid < 16) {
        float zt = 0.f, st = 0.f;
        #pragma unroll
        for (int j = 0; j < 16; j++) { zt += zr[tid + j*16]; st += sr[tid + j*16]; }
        g_S[cb*Oo + tid] = st / zt;
    }
}

// ---------------------------------------------------------------------------
// K_red: global squash. mode 0: s from g_part (scaled 1/R), V = s*f.
//        mode 1: s from g_S, V += s*f.   mode 2: s from g_S, out = s*f.
// f = sqrt(n2)/(1+n2), n2 = global sum of s^2 (squash with global Frobenius
// norm: v = scale*s/n = s*n/(1+n2)). Single block.
// ---------------------------------------------------------------------------
__global__ __launch_bounds__(1024) void k_red(int mode, float* __restrict__ outp) {
    const int tid = threadIdx.x;
    float sv[NS/1024];          // 20 per thread
    float sumsq = 0.f;
    #pragma unroll
    for (int k = 0; k < NS/1024; k++) {
        const int i = tid + k*1024;
        float s;
        if (mode == 0) {
            s = 0.f;
            #pragma unroll
            for (int j = 0; j < NRT; j++) s += g_part[i*NRT + j];
            s *= (1.0f / (float)Rr);
        } else {
            s = g_S[i];
        }
        sv[k] = s;
        sumsq += s*s;
    }
    __shared__ float red[1024];
    red[tid] = sumsq;
    __syncthreads();
    for (int st = 512; st > 0; st >>= 1) {
        if (tid < st) red[tid] += red[tid + st];
        __syncthreads();
    }
    const float n2 = red[0];
    const float f = sqrtf(n2) / (1.0f + n2);
    #pragma unroll
    for (int k = 0; k < NS/1024; k++) {
        const int i = tid + k*1024;
        if (mode == 0)       g_V[i] = sv[k] * f;
        else if (mode == 1)  g_V[i] += sv[k] * f;
        else                 outp[i] = sv[k] * f;
    }
}

// ---------------------------------------------------------------------------
extern "C" void kernel_launch(void* const* d_in, const int* in_sizes, int n_in,
                              void* d_out, int out_size) {
    const float* x = (const float*)d_in[0];   // [128,1152,8]
    const float* W = (const float*)d_in[1];   // [10,1152,8,16]
    // d_in[2] = num_iterations (== 3, fixed by problem setup)
    float* out = (float*)d_out;               // [10,128,1,1,16] = 20480 floats

    (void)in_sizes; (void)n_in; (void)out_size;

    k_u<<<dim3(NRT, Cc), 256>>>(x, W);
    k_red<<<1, 1024>>>(0, nullptr);           // iter 1 (uniform softmax) + squash
    k_iter<<<dim3(Bb, Cc), 256>>>();          // iter 2 softmax-weighted sums
    k_red<<<1, 1024>>>(1, nullptr);           // squash + V update
    k_iter<<<dim3(Bb, Cc), 256>>>();          // iter 3
    k_red<<<1, 1024>>>(2, out);               // final squash -> output
}

// round 3
// speedup vs baseline: 2.1188x; 2.1188x over previous
#include <cuda_runtime.h>
#include <cuda_fp16.h>
#include <math.h>

#define Bb 128
#define Rr 1152
#define CI 8
#define Cc 10
#define Oo 16
#define NCB (Cc*Bb)      /* 1280 */
#define NS  (NCB*Oo)     /* 20480 */
#define RT 32
#define NRT (Rr/RT)      /* 36 */

// Static device scratch (no runtime allocation)
__device__ __half g_uh[(size_t)Cc*Bb*Rr*Oo];  // 47 MB, u in fp16
__device__ float2 g_S0[NS/2];                 // atomic accumulators for iter-1 sums
__device__ float  g_S[NS];                    // per-iteration weighted sums s
__device__ float  g_V[NS];                    // accumulated v, pre-scaled by log2(e)

// ---------------------------------------------------------------------------
// fast 2^z via magic-number round + degree-5 poly (FMA pipe only, no MUFU)
// valid for any z that keeps the result in normal fp32 range; abs err ~2e-6.
// ---------------------------------------------------------------------------
__device__ __forceinline__ float fexp2f(float z) {
    const float MAGIC = 12582912.0f;           // 2^23 + 2^22
    float t  = z + MAGIC;                      // round-to-nearest int in low bits
    float f  = z - (t - MAGIC);                // frac in [-0.5, 0.5]
    int   nb = __float_as_int(t) << 23;        // n * 2^23 (low bits of magic are 0)
    float p  = 0.0013333558f;
    p = fmaf(p, f, 0.0096181298f);
    p = fmaf(p, f, 0.0555041087f);
    p = fmaf(p, f, 0.2402265070f);
    p = fmaf(p, f, 0.6931471806f);
    p = fmaf(p, f, 1.0f);
    return __int_as_float(__float_as_int(p) + nb);
}

// ---------------------------------------------------------------------------
// k_u: u[c,b,r,o] = sum_i x[b,r,i]*W[c,r,i,o]; store fp16; accumulate
// sum_r u into g_S0 (for iteration 1's uniform softmax: s1 = mean_r u).
// grid (NRT, C) = 360 CTAs, 256 threads. No barriers. W in registers.
// Thread: one r (= r0 + tid>>3), one o-pair (o = 2*(tid&7), +1).
// ---------------------------------------------------------------------------
__global__ __launch_bounds__(256) void k_u(const float* __restrict__ x,
                                           const float* __restrict__ W)
{
    const int rt  = blockIdx.x, c = blockIdx.y;
    const int tid = threadIdx.x;
    const int o2  = tid & 7;
    const int rl  = tid >> 3;          // 0..31
    const int r   = rt * RT + rl;

    // W slice for this thread: w0/w1[i] = W[c,r,i,2*o2 / 2*o2+1]
    float w0[8], w1[8];
    {
        const float* Wp = W + (((size_t)c*Rr + r)*CI)*Oo + 2*o2;
        #pragma unroll
        for (int i = 0; i < 8; i++) {
            float2 v = *(const float2*)(Wp + i*Oo);
            w0[i] = v.x; w1[i] = v.y;
        }
    }

    const float4* xp = (const float4*)x;
    const size_t  xstep = (size_t)Rr*CI/4;          // per-b float4 stride
    size_t xbase = (size_t)r*CI/4;

    half2* udst = (half2*)g_uh + ((size_t)c*Bb*Rr + r)*8 + o2;  // +b*Rr*8 per b

    float4 xa = xp[xbase], xb = xp[xbase+1];
    for (int b = 0; b < Bb; b++) {
        float4 na, nb;
        if (b + 1 < Bb) {
            size_t nx = xbase + (size_t)(b+1)*xstep;
            na = xp[nx]; nb = xp[nx+1];
        }
        float u0, u1;
        u0 =           xa.x*w0[0];        u1 =           xa.x*w1[0];
        u0 = fmaf(xa.y, w0[1], u0);       u1 = fmaf(xa.y, w1[1], u1);
        u0 = fmaf(xa.z, w0[2], u0);       u1 = fmaf(xa.z, w1[2], u1);
        u0 = fmaf(xa.w, w0[3], u0);       u1 = fmaf(xa.w, w1[3], u1);
        u0 = fmaf(xb.x, w0[4], u0);       u1 = fmaf(xb.x, w1[4], u1);
        u0 = fmaf(xb.y, w0[5], u0);       u1 = fmaf(xb.y, w1[5], u1);
        u0 = fmaf(xb.z, w0[6], u0);       u1 = fmaf(xb.z, w1[6], u1);
        u0 = fmaf(xb.w, w0[7], u0);       u1 = fmaf(xb.w, w1[7], u1);

        udst[(size_t)b*Rr*8] = __floats2half2_rn(u0, u1);

        // warp-reduce over the 4 r-rows this warp holds (lane bits 3,4)
        float p0 = u0, p1 = u1;
        p0 += __shfl_xor_sync(0xffffffffu, p0, 8);
        p1 += __shfl_xor_sync(0xffffffffu, p1, 8);
        p0 += __shfl_xor_sync(0xffffffffu, p0, 16);
        p1 += __shfl_xor_sync(0xffffffffu, p1, 16);
        if ((tid & 31) < 8)
            atomicAdd(&g_S0[(c*Bb + b)*8 + o2], make_float2(p0, p1));

        xa = na; xb = nb;
    }
}

// ---------------------------------------------------------------------------
// k_it: per (c,b): e_r = 2^(u*Vhat), s[o] = sum_r e*u / sum_r e.
// grid (B/2, C) = 640 CTAs, 256 threads, 2 b's per CTA sequentially.
// Thread covers o = p..p+7 (p = 8*(tid&1)) across its element chunks.
// ---------------------------------------------------------------------------
__global__ __launch_bounds__(256) void k_it()
{
    const int bx = blockIdx.x, c = blockIdx.y;
    const int tid = threadIdx.x;
    const int p = (tid & 1) * 8;
    __shared__ float zs[256*8];
    __shared__ float ss[256*8];

    for (int bb = 0; bb < 2; bb++) {
        const int b  = bx*2 + bb;
        const int cb = c*Bb + b;

        float V[8];
        #pragma unroll
        for (int j = 0; j < 8; j++) V[j] = g_V[cb*16 + p + j];   // already * log2e

        const float4* up = (const float4*)(g_uh + (size_t)cb*Rr*Oo);
        float z[8], s[8];
        #pragma unroll
        for (int j = 0; j < 8; j++) { z[j] = 0.f; s[j] = 0.f; }

        #pragma unroll 3
        for (int k = 0; k < 9; k++) {
            float4 raw = up[tid + k*256];
            const half2* hp = (const half2*)&raw;
            #pragma unroll
            for (int j = 0; j < 4; j++) {
                float2 f2 = __half22float2(hp[j]);
                float e0 = fexp2f(f2.x * V[2*j]);
                float e1 = fexp2f(f2.y * V[2*j+1]);
                z[2*j]   += e0;  s[2*j]   = fmaf(e0, f2.x, s[2*j]);
                z[2*j+1] += e1;  s[2*j+1] = fmaf(e1, f2.y, s[2*j+1]);
            }
        }

        const int row = (tid >> 1) + (tid & 1)*128;   // even threads rows 0..127
        #pragma unroll
        for (int j = 0; j < 8; j++) { zs[row*8+j] = z[j]; ss[row*8+j] = s[j]; }
        __syncthreads();
        if (tid < 16) {
            const int base = (tid & 8) ? 128*8 : 0;
            const int col  = tid & 7;
            float zt = 0.f, st = 0.f;
            #pragma unroll 8
            for (int t = 0; t < 128; t++) {
                zt += zs[base + t*8 + col];
                st += ss[base + t*8 + col];
            }
            g_S[cb*16 + tid] = st / zt;
        }
        __syncthreads();
    }
}

// ---------------------------------------------------------------------------
// k_red: global squash. n2 = sum s^2 (global Frobenius), f = sqrt(n2)/(1+n2).
// mode 0: s = g_S0/R,  g_V  = s*f*log2e
// mode 1: s = g_S,     g_V += s*f*log2e
// mode 2: s = g_S,     out  = s*f
// ---------------------------------------------------------------------------
__global__ __launch_bounds__(1024) void k_red(int mode, float* __restrict__ outp)
{
    const int tid = threadIdx.x;
    const float4* src = (mode == 0) ? (const float4*)g_S0 : (const float4*)g_S;
    float4 sv[5];
    float sumsq = 0.f;
    #pragma unroll
    for (int k = 0; k < 5; k++) {
        float4 v = src[tid + k*1024];
        if (mode == 0) {
            const float inv = 1.0f / (float)Rr;
            v.x *= inv; v.y *= inv; v.z *= inv; v.w *= inv;
        }
        sv[k] = v;
        sumsq += v.x*v.x + v.y*v.y + v.z*v.z + v.w*v.w;
    }
    __shared__ float red[1024];
    red[tid] = sumsq;
    __syncthreads();
    for (int st = 512; st > 0; st >>= 1) {
        if (tid < st) red[tid] += red[tid + st];
        __syncthreads();
    }
    const float n2 = red[0];
    const float f  = sqrtf(n2) / (1.0f + n2);
    const float L2E = 1.4426950408889634f;

    #pragma unroll
    for (int k = 0; k < 5; k++) {
        float4 v = sv[k];
        if (mode == 2) {
            float4 o = make_float4(v.x*f, v.y*f, v.z*f, v.w*f);
            ((float4*)outp)[tid + k*1024] = o;
        } else {
            const float g = f * L2E;
            float4 o = make_float4(v.x*g, v.y*g, v.z*g, v.w*g);
            if (mode == 1) {
                float4 old = ((float4*)g_V)[tid + k*1024];
                o.x += old.x; o.y += old.y; o.z += old.z; o.w += old.w;
            }
            ((float4*)g_V)[tid + k*1024] = o;
        }
    }
}

// ---------------------------------------------------------------------------
extern "C" void kernel_launch(void* const* d_in, const int* in_sizes, int n_in,
                              void* d_out, int out_size)
{
    const float* x = (const float*)d_in[0];   // [128,1152,8]
    const float* W = (const float*)d_in[1];   // [10,1152,8,16]
    float* out = (float*)d_out;               // 20480 floats
    (void)in_sizes; (void)n_in; (void)out_size;

    void* s0 = nullptr;
    cudaGetSymbolAddress(&s0, g_S0);
    cudaMemsetAsync(s0, 0, NS*sizeof(float), 0);

    k_u  <<<dim3(NRT, Cc), 256>>>(x, W);
    k_red<<<1, 1024>>>(0, nullptr);           // iter 1 (uniform) + squash
    k_it <<<dim3(Bb/2, Cc), 256>>>();         // iter 2
    k_red<<<1, 1024>>>(1, nullptr);
    k_it <<<dim3(Bb/2, Cc), 256>>>();         // iter 3
    k_red<<<1, 1024>>>(2, out);               // final squash -> output
}